// round 15
// baseline (speedup 1.0000x reference)
#include <cuda_runtime.h>
#include <cstdint>
#include <cstddef>

// Problem constants
#define BB 4
#define SS 2048
#define EE 1024
#define HH 16
#define DD 64
#define MTOK (BB * SS)     // 8192
#define SCALE 0.125f

// int8 GEMM tiling
#define RSTR 80                         // bytes per smem row (64 data + 16 pad)
#define TILEB (128 * RSTR)              // 10240 B per limb tile
#define STAGEB (4 * TILEB)              // A1 A2 B1 B2
#define SMEM_BYTES (2 * STAGEB)         // 81920 B

// Triangular block decode tables for the symmetric G GEMM (36 upper blocks).
__constant__ unsigned char c_tri_i[36] = {
    0,0,0,0,0,0,0,0, 1,1,1,1,1,1,1, 2,2,2,2,2,2, 3,3,3,3,3, 4,4,4,4, 5,5,5, 6,6, 7};
__constant__ unsigned char c_tri_j[36] = {
    0,1,2,3,4,5,6,7, 1,2,3,4,5,6,7, 2,3,4,5,6,7, 3,4,5,6,7, 4,5,6,7, 5,6,7, 6,7, 7};

// ---------------------------------------------------------------------------
// Scratch
// ---------------------------------------------------------------------------
__device__ float g_gf[BB * EE * EE];           // G_off = X^T X minus diag
__device__ float g_gd[BB * EE];                // diag(G)
__device__ float g_tf[BB * EE * EE];           // T = G Wv^T (+diag term)
__device__ float g_wqtf[EE * EE];              // Wq^T [e][j]
__device__ float g_wvtf[EE * EE];              // Wv^T [e][c]
__device__ float g_pt[BB][EE][EE];             // P^T [b][c][j]
__device__ float g_utf[BB * EE * EE];          // U^T [b][c][e]
__device__ int   g_cmax[BB * EE];              // per-(b,e) |X| max (fp32 bits)

__device__ unsigned char g_xa1[MTOK * EE], g_xa2[MTOK * EE];         // X rows
__device__ unsigned char g_xta1[BB * EE * SS], g_xta2[BB * EE * SS]; // X^T rows
__device__ unsigned char g_ga1[BB * EE * EE], g_ga2[BB * EE * EE];
__device__ unsigned char g_wv1[EE * EE], g_wv2[EE * EE];
__device__ unsigned char g_wqt1[EE * EE], g_wqt2[EE * EE];
__device__ unsigned char g_pta1[BB * EE * EE], g_pta2[BB * EE * EE];
__device__ unsigned char g_uta1[BB * EE * EE], g_uta2[BB * EE * EE];
__device__ float g_sx[MTOK], g_sxt[BB * EE], g_sg[BB * EE], g_swv[EE],
                 g_swqt[EE], g_spt[BB * EE], g_sut[BB * EE];

// ---------------------------------------------------------------------------
// Helpers
// ---------------------------------------------------------------------------
__device__ __forceinline__ uint32_t smem_u32(const void* p) {
    uint32_t a;
    asm("{ .reg .u64 t; cvta.to.shared.u64 t, %1; cvt.u32.u64 %0, t; }" : "=r"(a) : "l"(p));
    return a;
}
__device__ __forceinline__ void cpasync16(uint32_t s, const void* g) {
    asm volatile("cp.async.cg.shared.global [%0], [%1], 16;" :: "r"(s), "l"(g));
}
#define CP_COMMIT() asm volatile("cp.async.commit_group;" ::: "memory")
#define CP_WAIT(n)  asm volatile("cp.async.wait_group %0;" :: "n"(n) : "memory")

__device__ __forceinline__ void imma(int* c, const uint32_t* a, const uint32_t* b) {
    asm volatile(
        "mma.sync.aligned.m16n8k32.row.col.s32.s8.s8.s32 "
        "{%0,%1,%2,%3}, {%4,%5,%6,%7}, {%8,%9}, {%0,%1,%2,%3};"
        : "+r"(c[0]), "+r"(c[1]), "+r"(c[2]), "+r"(c[3])
        : "r"(a[0]), "r"(a[1]), "r"(a[2]), "r"(a[3]), "r"(b[0]), "r"(b[1]));
}
__device__ __forceinline__ uint32_t lds32(uint32_t a) {
    uint32_t v;
    asm volatile("ld.shared.b32 %0, [%1];" : "=r"(v) : "r"(a));
    return v;
}

// Pack 4 s32 (range fits s8) into one u32: bytes [b0,b1,b2,b3].
__device__ __forceinline__ uint32_t pack4(int b0, int b1, int b2, int b3) {
    uint32_t t, r;
    asm("cvt.pack.sat.s8.s32.b32 %0, %1, %2, 0;" : "=r"(t) : "r"(b3), "r"(b2));
    asm("cvt.pack.sat.s8.s32.b32 %0, %1, %2, %3;" : "=r"(r) : "r"(b1), "r"(b0), "r"(t));
    return r;
}

// Quantize one fp32 value: q1 = rint(v*inv), q2 = rint((v*inv-q1)*252)
__device__ __forceinline__ void qsplit(float v, float inv, int& q1, int& q2) {
    float t = v * inv;
    q1 = __float2int_rn(t);
    q2 = __float2int_rn((t - (float)q1) * 252.0f);
}

// ---------------------------------------------------------------------------
// clear_cmax
// ---------------------------------------------------------------------------
__global__ __launch_bounds__(256) void clear_cmax() {
    g_cmax[blockIdx.x * 1024 + threadIdx.x * 4 + 0] = 0;
    g_cmax[blockIdx.x * 1024 + threadIdx.x * 4 + 1] = 0;
    g_cmax[blockIdx.x * 1024 + threadIdx.x * 4 + 2] = 0;
    g_cmax[blockIdx.x * 1024 + threadIdx.x * 4 + 3] = 0;
}

// ---------------------------------------------------------------------------
// quant_row_256
// ---------------------------------------------------------------------------
__device__ __forceinline__ void quant_row_256(const float* __restrict__ src,
                                              unsigned char* __restrict__ q1,
                                              unsigned char* __restrict__ q2,
                                              float* __restrict__ sdeq, int len) {
    const int tid = threadIdx.x;
    const int L = len >> 10;
    const float4* p = (const float4*)src;

    __shared__ float wmax[8];
    __shared__ float sinv;

    float4 v[2];
    float m = 0.0f;
    for (int i = 0; i < L; ++i) {
        v[i] = p[tid + i * 256];
        m = fmaxf(m, fmaxf(fmaxf(fabsf(v[i].x), fabsf(v[i].y)),
                           fmaxf(fabsf(v[i].z), fabsf(v[i].w))));
    }
#pragma unroll
    for (int o = 16; o > 0; o >>= 1) m = fmaxf(m, __shfl_xor_sync(0xFFFFFFFFu, m, o));
    if ((tid & 31) == 0) wmax[tid >> 5] = m;
    __syncthreads();
    if (tid == 0) {
        float mm = wmax[0];
#pragma unroll
        for (int i = 1; i < 8; ++i) mm = fmaxf(mm, wmax[i]);
        *sdeq = mm * (1.0f / 126.0f);
        sinv = (mm > 0.0f) ? 126.0f / mm : 0.0f;
    }
    __syncthreads();
    const float inv = sinv;

    for (int i = 0; i < L; ++i) {
        int a0, a1, a2, a3, b0, b1, b2, b3;
        qsplit(v[i].x, inv, a0, b0);
        qsplit(v[i].y, inv, a1, b1);
        qsplit(v[i].z, inv, a2, b2);
        qsplit(v[i].w, inv, a3, b3);
        ((uint32_t*)q1)[tid + i * 256] = pack4(a0, a1, a2, a3);
        ((uint32_t*)q2)[tid + i * 256] = pack4(b0, b1, b2, b3);
    }
}

__global__ __launch_bounds__(256) void quantize(const float* __restrict__ src,
                                                unsigned char* __restrict__ q1,
                                                unsigned char* __restrict__ q2,
                                                float* __restrict__ sdeq, int len) {
    const int row = blockIdx.x;
    quant_row_256(src + (size_t)row * len, q1 + (size_t)row * len,
                  q2 + (size_t)row * len, sdeq + row, len);
}

// ---------------------------------------------------------------------------
// stage1: [0,256) colmax of X (per (b,e)); [256,2304) Wq/Wv gather-transpose.
// ---------------------------------------------------------------------------
__global__ __launch_bounds__(256) void stage1(const float* __restrict__ x,
                                              const float* __restrict__ w) {
    const int bid = blockIdx.x;
    const int tid = threadIdx.x;

    if (bid < 256) {
        const int b = bid >> 6;
        const int s0 = (bid & 63) * 32;
        float m0 = 0, m1 = 0, m2 = 0, m3 = 0;
        const float4* p = (const float4*)(x + ((size_t)b * SS + s0) * EE) + tid;
#pragma unroll 4
        for (int r = 0; r < 32; ++r) {
            float4 v = p[r * 256];
            m0 = fmaxf(m0, fabsf(v.x));
            m1 = fmaxf(m1, fabsf(v.y));
            m2 = fmaxf(m2, fabsf(v.z));
            m3 = fmaxf(m3, fabsf(v.w));
        }
        int* dst = g_cmax + b * EE + tid * 4;
        atomicMax(dst + 0, __float_as_int(m0));
        atomicMax(dst + 1, __float_as_int(m1));
        atomicMax(dst + 2, __float_as_int(m2));
        atomicMax(dst + 3, __float_as_int(m3));
    } else {
        __shared__ float t[32][33];
        const int tt = bid - 256;
        const int which = tt >> 10;           // 0 -> Wq^T, 1 -> Wv^T
        const int rem = tt & 1023;
        const int e0 = (rem & 31) * 32;
        const int j0 = (rem >> 5) * 32;
        const int off = which ? 128 : 0;
        float* dst = which ? g_wvtf : g_wqtf;
        const int c = tid & 31, r0 = tid >> 5;
#pragma unroll
        for (int p = 0; p < 4; ++p) {
            const int j = j0 + r0 + p * 8;
            const int srow = (j >> 6) * 192 + off + (j & 63);
            t[r0 + p * 8][c] = w[(size_t)srow * EE + e0 + c];
        }
        __syncthreads();
#pragma unroll
        for (int p = 0; p < 4; ++p) {
            const int r = r0 + p * 8;
            dst[(size_t)(e0 + r) * EE + j0 + c] = t[c][r];
        }
    }
}

// ---------------------------------------------------------------------------
// stage2: fused quantization (X^T transpose+quant, X rows, Wv, Wq^T).
// ---------------------------------------------------------------------------
__global__ __launch_bounds__(256) void stage2(const float* __restrict__ x,
                                              const float* __restrict__ w) {
    const int bid = blockIdx.x;
    const int tid = threadIdx.x;

    if (bid < 2048) {
        __shared__ float ts[32][133];
        const int b = bid >> 9;
        const int rem = bid & 511;
        const int s0 = (rem & 15) * 128;
        const int e0 = (rem >> 4) * 32;

#pragma unroll
        for (int i = 0; i < 4; ++i) {
            const int idx = i * 256 + tid;
            const int sl = idx >> 3;
            const int e4 = (idx & 7) * 4;
            float4 v = *(const float4*)&x[((size_t)b * SS + s0 + sl) * EE + e0 + e4];
            ts[e4 + 0][sl] = v.x; ts[e4 + 1][sl] = v.y;
            ts[e4 + 2][sl] = v.z; ts[e4 + 3][sl] = v.w;
        }
        __syncthreads();

        const int el = tid >> 3;
        const int sg = (tid & 7) * 16;
        const float cm = __int_as_float(g_cmax[b * EE + e0 + el]);
        const float inv = (cm > 0.0f) ? 126.0f / cm : 0.0f;
        if (s0 == 0 && (tid & 7) == 0) g_sxt[b * EE + e0 + el] = cm * (1.0f / 126.0f);

        uint32_t o1[4], o2[4];
#pragma unroll
        for (int q = 0; q < 4; ++q) {
            int a0, a1, a2, a3, b0, b1, b2, b3;
            qsplit(ts[el][sg + q * 4 + 0], inv, a0, b0);
            qsplit(ts[el][sg + q * 4 + 1], inv, a1, b1);
            qsplit(ts[el][sg + q * 4 + 2], inv, a2, b2);
            qsplit(ts[el][sg + q * 4 + 3], inv, a3, b3);
            o1[q] = pack4(a0, a1, a2, a3);
            o2[q] = pack4(b0, b1, b2, b3);
        }
        const size_t go = ((size_t)(b * EE + e0 + el)) * SS + s0 + sg;
        *(uint4*)&g_xta1[go] = make_uint4(o1[0], o1[1], o1[2], o1[3]);
        *(uint4*)&g_xta2[go] = make_uint4(o2[0], o2[1], o2[2], o2[3]);
    } else if (bid < 2048 + MTOK) {
        const int r = bid - 2048;
        quant_row_256(x + (size_t)r * EE, g_xa1 + (size_t)r * EE,
                      g_xa2 + (size_t)r * EE, g_sx + r, EE);
    } else if (bid < 2048 + MTOK + EE) {
        const int r = bid - 2048 - MTOK;
        const int sr = (r >> 6) * 192 + 128 + (r & 63);
        quant_row_256(w + (size_t)sr * EE, g_wv1 + (size_t)r * EE,
                      g_wv2 + (size_t)r * EE, g_swv + r, EE);
    } else {
        const int r = bid - 2048 - MTOK - EE;
        quant_row_256(g_wqtf + (size_t)r * EE, g_wqt1 + (size_t)r * EE,
                      g_wqt2 + (size_t)r * EE, g_swqt + r, EE);
    }
}

// ---------------------------------------------------------------------------
// int8 2-limb GEMM core — nt-pair software-pipelined inner loop:
// B-fragment LDS for the next nt-pair are issued between the current pair's
// IMMAs so the smem crossbar and tensor pipe run concurrently.
// emode 0: G (triangular LUT grid, diag extracted, mirrored), kd=2048
// emode 1: T (+diag term).  emode 2: U^T.  emode 3: out.
// ---------------------------------------------------------------------------
__global__ __launch_bounds__(256, 1) void gemm_i8(
    const unsigned char* __restrict__ A1b, const unsigned char* __restrict__ A2b,
    const unsigned char* __restrict__ B1b, const unsigned char* __restrict__ B2b,
    const float* __restrict__ sAb, const float* __restrict__ sBb,
    float* __restrict__ Out, int kd, int aZ, int bZ, int emode) {
    extern __shared__ unsigned char smem[];
    const int tid = threadIdx.x;
    const int wid = tid >> 5, lane = tid & 31;
    const int g = lane >> 2, tg = lane & 3;
    const int warp_m = wid & 3;
    const int warp_n = wid >> 2;
    const int z = blockIdx.z;

    int bm, bn;
    if (emode == 0) {
        bm = (int)c_tri_i[blockIdx.x] * 128;
        bn = (int)c_tri_j[blockIdx.x] * 128;
    } else {
        bn = blockIdx.x * 128;
        bm = blockIdx.y * 128;
    }

    const unsigned char* A1 = A1b + (size_t)(z * aZ + bm) * kd;
    const unsigned char* A2 = A2b + (size_t)(z * aZ + bm) * kd;
    const unsigned char* B1 = B1b + (size_t)(z * bZ + bn) * kd;
    const unsigned char* B2 = B2b + (size_t)(z * bZ + bn) * kd;
    const float* sA = sAb + z * aZ + bm;
    const float* sB = sBb + z * bZ + bn;

    const uint32_t sb = smem_u32(smem);

    int acc11[2][8][4], accmx[2][8][4];
#pragma unroll
    for (int mt = 0; mt < 2; ++mt)
#pragma unroll
        for (int nt = 0; nt < 8; ++nt)
#pragma unroll
            for (int i = 0; i < 4; ++i) { acc11[mt][nt][i] = 0; accmx[mt][nt][i] = 0; }

    auto load_chunk = [&](int s, int k0) {
        const uint32_t base = sb + s * STAGEB;
#pragma unroll
        for (int it = 0; it < 2; ++it) {
            const int id = tid + it * 256;
            const int row = id >> 2;
            const int c16 = (id & 3) * 16;
            const uint32_t so = row * RSTR + c16;
            const size_t go = (size_t)row * kd + k0 + c16;
            cpasync16(base + so,              A1 + go);
            cpasync16(base + TILEB + so,      A2 + go);
            cpasync16(base + 2 * TILEB + so,  B1 + go);
            cpasync16(base + 3 * TILEB + so,  B2 + go);
        }
        CP_COMMIT();
    };

    load_chunk(0, 0);

    const int NK = kd >> 6;
    for (int kc = 0; kc < NK; ++kc) {
        const int s = kc & 1;
        if (kc + 1 < NK) {
            load_chunk(1 - s, (kc + 1) * 64);
            CP_WAIT(1);
        } else {
            CP_WAIT(0);
        }
        __syncthreads();

        const uint32_t stg = sb + s * STAGEB;
#pragma unroll
        for (int ks = 0; ks < 2; ++ks) {
            const uint32_t kof = ks * 32 + tg * 4;
            // A fragments for this ks (both limbs).
            uint32_t a1f[2][4], a2f[2][4];
#pragma unroll
            for (int mt = 0; mt < 2; ++mt) {
                const uint32_t r0 = stg + (warp_m * 32 + mt * 16 + g) * RSTR + kof;
                a1f[mt][0] = lds32(r0);
                a1f[mt][1] = lds32(r0 + 8 * RSTR);
                a1f[mt][2] = lds32(r0 + 16);
                a1f[mt][3] = lds32(r0 + 8 * RSTR + 16);
                a2f[mt][0] = lds32(r0 + TILEB);
                a2f[mt][1] = lds32(r0 + TILEB + 8 * RSTR);
                a2f[mt][2] = lds32(r0 + TILEB + 16);
                a2f[mt][3] = lds32(r0 + TILEB + 8 * RSTR + 16);
            }
            // B fragments: double-buffered nt-pairs. buf[p&1] = current pair.
            uint32_t b1f[2][2][2], b2f[2][2][2];   // [buf][ntInPair][reg]
            const uint32_t bbase = stg + 2 * TILEB + (warp_n * 64 + g) * RSTR + kof;
#pragma unroll
            for (int q = 0; q < 2; ++q) {
                const uint32_t r0 = bbase + q * 8 * RSTR;
                b1f[0][q][0] = lds32(r0);
                b1f[0][q][1] = lds32(r0 + 16);
                b2f[0][q][0] = lds32(r0 + TILEB);
                b2f[0][q][1] = lds32(r0 + TILEB + 16);
            }
#pragma unroll
            for (int p = 0; p < 4; ++p) {
                const int cb = p & 1;
                // Prefetch next pair's B fragments (overlaps with IMMAs below).
                if (p < 3) {
#pragma unroll
                    for (int q = 0; q < 2; ++q) {
                        const uint32_t r0 = bbase + ((p + 1) * 2 + q) * 8 * RSTR;
                        b1f[cb ^ 1][q][0] = lds32(r0);
                        b1f[cb ^ 1][q][1] = lds32(r0 + 16);
                        b2f[cb ^ 1][q][0] = lds32(r0 + TILEB);
                        b2f[cb ^ 1][q][1] = lds32(r0 + TILEB + 16);
                    }
                }
                const int n0 = p * 2, n1 = p * 2 + 1;
                // 12 IMMAs; dependent accmx writes kept >= 4 apart.
                imma(acc11[0][n0], a1f[0], b1f[cb][0]);
                imma(acc11[1][n0], a1f[1], b1f[cb][0]);
                imma(acc11[0][n1], a1f[0], b1f[cb][1]);
                imma(acc11[1][n1], a1f[1], b1f[cb][1]);
                imma(accmx[0][n0], a1f[0], b2f[cb][0]);
                imma(accmx[1][n0], a1f[1], b2f[cb][0]);
                imma(accmx[0][n1], a1f[0], b2f[cb][1]);
                imma(accmx[1][n1], a1f[1], b2f[cb][1]);
                imma(accmx[0][n0], a2f[0], b1f[cb][0]);
                imma(accmx[1][n0], a2f[1], b1f[cb][0]);
                imma(accmx[0][n1], a2f[0], b1f[cb][1]);
                imma(accmx[1][n1], a2f[1], b1f[cb][1]);
            }
        }
        __syncthreads();
    }

    // Epilogue: dequant + runtime-mode store.
#pragma unroll
    for (int mt = 0; mt < 2; ++mt) {
        const int rb = warp_m * 32 + mt * 16 + g;
        const float sa0 = sA[rb], sa1 = sA[rb + 8];
#pragma unroll
        for (int nt = 0; nt < 8; ++nt) {
            const int coff = warp_n * 64 + nt * 8 + 2 * tg;
            const float sb0 = sB[coff], sb1 = sB[coff + 1];
            const int col = bn + coff;
#pragma unroll
            for (int half = 0; half < 2; ++half) {
                const int rl = bm + rb + half * 8;
                const float sa = half ? sa1 : sa0;
                float v0 = ((float)acc11[mt][nt][half * 2 + 0]
                            + (float)accmx[mt][nt][half * 2 + 0] * (1.0f / 252.0f)) * sa * sb0;
                float v1 = ((float)acc11[mt][nt][half * 2 + 1]
                            + (float)accmx[mt][nt][half * 2 + 1] * (1.0f / 252.0f)) * sa * sb1;
                if (emode == 0) {
                    if (rl == col)     { g_gd[z * EE + rl] = v0; v0 = 0.0f; }
                    if (rl == col + 1) { g_gd[z * EE + rl] = v1; v1 = 0.0f; }
                    *(float2*)&g_gf[((size_t)z * EE + rl) * EE + col] = make_float2(v0, v1);
                    if (bm != bn) {
                        g_gf[((size_t)z * EE + col) * EE + rl] = v0;
                        g_gf[((size_t)z * EE + col + 1) * EE + rl] = v1;
                    }
                } else if (emode == 1) {
                    const float gd = g_gd[z * EE + rl];
                    const float2 wv = *(const float2*)&g_wvtf[(size_t)rl * EE + col];
                    v0 += gd * wv.x;
                    v1 += gd * wv.y;
                    *(float2*)&g_tf[((size_t)z * EE + rl) * EE + col] = make_float2(v0, v1);
                } else if (emode == 2) {
                    *(float2*)&g_utf[((size_t)z * EE + rl) * EE + col] = make_float2(v0, v1);
                } else {
                    *(float2*)&Out[((size_t)z * SS + rl) * EE + col] = make_float2(v0, v1);
                }
            }
        }
    }
}

// ---------------------------------------------------------------------------
// heads: fused mstep + make_p.  Grid (HH, BB), 256 threads.
// ---------------------------------------------------------------------------
__global__ __launch_bounds__(256) void heads(const float* __restrict__ w,
                                             const float* __restrict__ w_o) {
    const int h = blockIdx.x, b = blockIdx.y;
    const int tid = threadIdx.x;
    const int tx = tid & 15;
    const int ty = tid >> 4;

    __shared__ float Msh[64][68];
    __shared__ float buf[64][68];

    float acc[4][4];
#pragma unroll
    for (int i = 0; i < 4; ++i)
#pragma unroll
        for (int j = 0; j < 4; ++j) acc[i][j] = 0.0f;

    for (int e0 = 0; e0 < EE; e0 += 32) {
#pragma unroll
        for (int it = 0; it < 2; ++it) {
            const int fid = tid + it * 256;
            const int d1 = fid >> 3;
            const int c4 = (fid & 7) * 4;
            float4 v = *(const float4*)&w[(size_t)(h * 192 + 64 + d1) * EE + e0 + c4];
            buf[c4 + 0][d1] = v.x; buf[c4 + 1][d1] = v.y;
            buf[c4 + 2][d1] = v.z; buf[c4 + 3][d1] = v.w;
        }
#pragma unroll
        for (int it = 0; it < 2; ++it) {
            const int fid = tid + it * 256;
            const int r = fid >> 4;
            const int c4 = (fid & 15) * 4;
            *(float4*)&buf[32 + r][c4] =
                *(const float4*)&g_tf[((size_t)b * EE + e0 + r) * EE + h * 64 + c4];
        }
        __syncthreads();
#pragma unroll 8
        for (int e = 0; e < 32; ++e) {
            float a[4], bb[4];
#pragma unroll
            for (int i = 0; i < 4; ++i) a[i] = buf[e][ty * 4 + i];
#pragma unroll
            for (int j = 0; j < 4; ++j) bb[j] = buf[32 + e][tx * 4 + j];
#pragma unroll
            for (int i = 0; i < 4; ++i)
#pragma unroll
                for (int j = 0; j < 4; ++j) acc[i][j] += a[i] * bb[j];
        }
        __syncthreads();
    }
#pragma unroll
    for (int i = 0; i < 4; ++i)
#pragma unroll
        for (int j = 0; j < 4; ++j)
            Msh[tx * 4 + j][ty * 4 + i] = SCALE * acc[i][j];
    __syncthreads();

    for (int c0 = 0; c0 < EE; c0 += 64) {
#pragma unroll
        for (int it = 0; it < 4; ++it) {
            const int fid = tid + it * 256;
            const int c = fid >> 4;
            const int d4 = (fid & 15) * 4;
            float4 v = *(const float4*)&w_o[(size_t)(c0 + c) * EE + h * 64 + d4];
            buf[d4 + 0][c] = v.x; buf[d4 + 1][c] = v.y;
            buf[d4 + 2][c] = v.z; buf[d4 + 3][c] = v.w;
        }
        __syncthreads();

        float a2[4][4];
#pragma unroll
        for (int i = 0; i < 4; ++i)
#pragma unroll
            for (int j = 0; j < 4; ++j) a2[i][j] = 0.0f;
#pragma unroll 8
        for (int d = 0; d < 64; ++d) {
            float a[4], bb[4];
#pragma unroll
            for (int i = 0; i < 4; ++i) a[i] = buf[d][ty * 4 + i];
#pragma unroll
            for (int j = 0; j < 4; ++j) bb[j] = Msh[d][tx * 4 + j];
#pragma unroll
            for (int i = 0; i < 4; ++i)
#pragma unroll
                for (int j = 0; j < 4; ++j) a2[i][j] += a[i] * bb[j];
        }
#pragma unroll
        for (int i = 0; i < 4; ++i) {
            float4 v;
            v.x = a2[i][0]; v.y = a2[i][1]; v.z = a2[i][2]; v.w = a2[i][3];
            *(float4*)&g_pt[b][c0 + ty * 4 + i][h * 64 + tx * 4] = v;
        }
        __syncthreads();
    }
}

// ---------------------------------------------------------------------------
// Launch
// ---------------------------------------------------------------------------
extern "C" void kernel_launch(void* const* d_in, const int* in_sizes, int n_in,
                              void* d_out, int out_size) {
    const float* x = (const float*)d_in[0];
    const float* w_qkv = (const float*)d_in[1];
    const float* w_o = (const float*)d_in[2];
    float* out = (float*)d_out;

    cudaFuncSetAttribute(gemm_i8, cudaFuncAttributeMaxDynamicSharedMemorySize, SMEM_BYTES);

    unsigned char *xa1, *xa2, *xta1, *xta2, *ga1, *ga2, *wv1, *wv2, *wqt1, *wqt2,
                  *pta1, *pta2, *uta1, *uta2;
    float *sx, *sxt, *sg, *swv, *swqt, *spt, *sut, *gf, *ptf, *utf;
    cudaGetSymbolAddress((void**)&xa1, g_xa1);   cudaGetSymbolAddress((void**)&xa2, g_xa2);
    cudaGetSymbolAddress((void**)&xta1, g_xta1); cudaGetSymbolAddress((void**)&xta2, g_xta2);
    cudaGetSymbolAddress((void**)&ga1, g_ga1);   cudaGetSymbolAddress((void**)&ga2, g_ga2);
    cudaGetSymbolAddress((void**)&wv1, g_wv1);   cudaGetSymbolAddress((void**)&wv2, g_wv2);
    cudaGetSymbolAddress((void**)&wqt1, g_wqt1); cudaGetSymbolAddress((void**)&wqt2, g_wqt2);
    cudaGetSymbolAddress((void**)&pta1, g_pta1); cudaGetSymbolAddress((void**)&pta2, g_pta2);
    cudaGetSymbolAddress((void**)&uta1, g_uta1); cudaGetSymbolAddress((void**)&uta2, g_uta2);
    cudaGetSymbolAddress((void**)&sx, g_sx);     cudaGetSymbolAddress((void**)&sxt, g_sxt);
    cudaGetSymbolAddress((void**)&sg, g_sg);     cudaGetSymbolAddress((void**)&swv, g_swv);
    cudaGetSymbolAddress((void**)&swqt, g_swqt); cudaGetSymbolAddress((void**)&spt, g_spt);
    cudaGetSymbolAddress((void**)&sut, g_sut);
    cudaGetSymbolAddress((void**)&gf, g_gf);
    cudaGetSymbolAddress((void**)&ptf, g_pt);    cudaGetSymbolAddress((void**)&utf, g_utf);

    // 0. clear column-max accumulators
    clear_cmax<<<4, 256>>>();
    // 1. colmax(X) + weight transposes
    stage1<<<256 + 2048, 256>>>(x, w_qkv);
    // 2. fused quantization
    stage2<<<2048 + MTOK + EE + EE, 256>>>(x, w_qkv);
    // 3. G = X^T X (triangular; diag extracted; mirrored)
    gemm_i8<<<dim3(36, 1, BB), 256, SMEM_BYTES>>>(
        xta1, xta2, xta1, xta2, sxt, sxt, nullptr, 2048, EE, EE, 0);
    // 4. quantize G
    quantize<<<BB * EE, 256>>>(gf, ga1, ga2, sg, EE);
    // 5. T = G Wv^T (+ diag term)
    gemm_i8<<<dim3(8, 8, BB), 256, SMEM_BYTES>>>(
        ga1, ga2, wv1, wv2, sg, swv, nullptr, 1024, EE, 0, 1);
    // 6. M + P^T fused
    heads<<<dim3(HH, BB), 256>>>(w_qkv, w_o);
    // 7. quantize P^T
    quantize<<<BB * EE, 256>>>(ptf, pta1, pta2, spt, EE);
    // 8. U^T = P^T Wq
    gemm_i8<<<dim3(8, 8, BB), 256, SMEM_BYTES>>>(
        pta1, pta2, wqt1, wqt2, spt, swqt, nullptr, 1024, EE, 0, 2);
    // 9. quantize U^T
    quantize<<<BB * EE, 256>>>(utf, uta1, uta2, sut, EE);
    // 10. out = X U
    gemm_i8<<<dim3(8, SS / 128, BB), 256, SMEM_BYTES>>>(
        xa1, xa2, uta1, uta2, sx, sut, out, 1024, SS, EE, 3);
}